// round 15
// baseline (speedup 1.0000x reference)
#include <cuda_runtime.h>
#include <cuda_bf16.h>
#include <cstdint>

#define BATCH   16384
#define SPC     16              // samples per CTA -> M = 128 rows
#define NBLK    (BATCH / SPC)   // 1024
#define THREADS 256

// ---- SMEM layout (bytes) ----
#define SM_A     0              // A hi: 128 rows x 528 B (264 bf16, padded)
#define A_STRIDE 528
#define SM_ALO   67584          // A lo: same shape
#define SM_W     135168         // 2 bufs x (whi 20480 + wlo 20480)
#define W_STRIDE 80             // 40 bf16 padded row (32 used)
#define WBUF     40960
#define SM_WO    217088         // float[512]
#define SM_B     219136         // float[3][256]
#define SM_W0    222208         // float[4][256]
#define SM_B0    226304         // float[256]
#define SM_X     227328         // float[64]
#define SMEM_TOTAL 227584
// vals overlay (final layer, fp32): rows 128 x 264 floats over [SM_A, SM_A+135168)
#define V_STRIDE 264

// weight scratch: [layer(3)][hi/lo(2)][n(256)][k(256)] bf16  (W^T: [n][k] = W[k][n])
__device__ __nv_bfloat16 g_wsplit[3][2][256][256];

// ============================ helpers ============================
__device__ __forceinline__ uint32_t smem_to_u32(const void* p) {
    uint32_t a;
    asm("{ .reg .u64 t; cvta.to.shared.u64 t, %1; cvt.u32.u64 %0, t; }"
        : "=r"(a) : "l"(p));
    return a;
}
__device__ __forceinline__ void cp_async16(uint32_t dst, const void* src) {
    asm volatile("cp.async.cg.shared.global [%0], [%1], 16;" :: "r"(dst), "l"(src));
}
#define CP_COMMIT() asm volatile("cp.async.commit_group;" ::: "memory")
#define CP_WAIT0()  asm volatile("cp.async.wait_group 0;" ::: "memory")

__device__ __forceinline__ void ldmatrix_x4(uint32_t* f, uint32_t addr) {
    asm volatile("ldmatrix.sync.aligned.m8n8.x4.shared.b16 {%0,%1,%2,%3}, [%4];"
        : "=r"(f[0]), "=r"(f[1]), "=r"(f[2]), "=r"(f[3]) : "r"(addr));
}
__device__ __forceinline__ void mma_bf16(float* d, const uint32_t* a,
                                         uint32_t b0, uint32_t b1) {
    asm volatile("mma.sync.aligned.m16n8k16.row.col.f32.bf16.bf16.f32 "
        "{%0,%1,%2,%3}, {%4,%5,%6,%7}, {%8,%9}, {%0,%1,%2,%3};"
        : "+f"(d[0]), "+f"(d[1]), "+f"(d[2]), "+f"(d[3])
        : "r"(a[0]), "r"(a[1]), "r"(a[2]), "r"(a[3]), "r"(b0), "r"(b1));
}

// fast accurate tanh: (e-1)/(e+1), e = exp(2a), clamped
__device__ __forceinline__ float ftanh(float a) {
    float ac = fminf(fmaxf(a, -40.f), 40.f);
    float e = __expf(2.f * ac);
    return __fdividef(e - 1.f, e + 1.f);
}
// coupled stream value: s=0 -> tanh; 1..4 -> t*a'; 5..7 -> t*a'' - 2 v t q^2
__device__ __forceinline__ float stream_val(int s, float d, float a0, float q) {
    const float v = ftanh(a0);
    const float tt = fmaf(-v, v, 1.f);
    if (s == 0) return v;
    if (s < 5)  return tt * d;
    return fmaf(tt, d, (-2.f * v * tt) * q * q);
}
// split fp32 pair -> packed bf16x2 hi and lo
__device__ __forceinline__ void split_pack(float v0, float v1,
                                           uint32_t& hi, uint32_t& lo) {
    __nv_bfloat16 h0 = __float2bfloat16(v0);
    __nv_bfloat16 h1 = __float2bfloat16(v1);
    __nv_bfloat16 l0 = __float2bfloat16(v0 - __bfloat162float(h0));
    __nv_bfloat16 l1 = __float2bfloat16(v1 - __bfloat162float(h1));
    __nv_bfloat162 hp(h0, h1), lp(l0, l1);
    hi = *reinterpret_cast<uint32_t*>(&hp);
    lo = *reinterpret_cast<uint32_t*>(&lp);
}

// ============================ prep kernel ============================
__global__ void prep_weights(const float* __restrict__ W1,
                             const float* __restrict__ W2,
                             const float* __restrict__ W3) {
    int l = blockIdx.x >> 8, n = blockIdx.x & 255, k = threadIdx.x;
    const float* W = (l == 0) ? W1 : (l == 1) ? W2 : W3;
    float w = W[k * 256 + n];
    __nv_bfloat16 hi = __float2bfloat16(w);
    g_wsplit[l][0][n][k] = hi;
    g_wsplit[l][1][n][k] = __float2bfloat16(w - __bfloat162float(hi));
}

// stream W chunk g (layer g/8, k-chunk g%8) into buffer g&1
__device__ __forceinline__ void load_chunk(uint32_t sb, int g, int tid) {
    const int l = g >> 3, c = g & 7;
    const __nv_bfloat16* base = &g_wsplit[0][0][0][0];
#pragma unroll
    for (int t = 0; t < 8; t++) {
        int i = tid + t * 256;
        int split = i >> 10, r = i & 1023, n = r >> 2, seg = r & 3;
        const __nv_bfloat16* src =
            base + (((size_t)(l * 2 + split)) << 16) + n * 256 + c * 32 + seg * 8;
        uint32_t dst = sb + SM_W + (uint32_t)(g & 1) * WBUF +
                       (uint32_t)split * 20480u + (uint32_t)n * W_STRIDE +
                       (uint32_t)seg * 16u;
        cp_async16(dst, src);
    }
}

// ============================ main kernel ============================
extern "C" __global__ void __launch_bounds__(THREADS, 1)
grad_mlp_tc(const float* __restrict__ x,
            const float* __restrict__ W0, const float* __restrict__ b0,
            const float* __restrict__ b1, const float* __restrict__ b2,
            const float* __restrict__ b3,
            const float* __restrict__ Wo, const float* __restrict__ bo,
            float* __restrict__ out) {
    extern __shared__ char sh[];
    const uint32_t sb = smem_to_u32(sh);
    const int tid = threadIdx.x;
    const int warp = tid >> 5, lane = tid & 31;
    const int warpM = warp >> 1, warpN = warp & 1;
    const int s = lane >> 2;             // stream id of this thread's D rows
    const int tig = lane & 3;
    const int qsl = ((s >= 5) ? (s - 4) : 0) * 4 + tig;   // shfl src for q
    // ldmatrix lane address components
    const int a_r = lane & 15;
    const int a_k = (lane >> 4) * 8;
    const int w_n = (lane & 7) + ((lane & 16) ? 8 : 0);
    const int w_k = (lane & 8) ? 8 : 0;

    // prefetch first weight chunk
    load_chunk(sb, 0, tid);
    CP_COMMIT();

    // stage small tables
    {
        float* woS = (float*)(sh + SM_WO);
        for (int i = tid; i < 512; i += THREADS) woS[i] = Wo[i];
        float* bS = (float*)(sh + SM_B);
        for (int i = tid; i < 256; i += THREADS) {
            bS[i] = b1[i]; bS[256 + i] = b2[i]; bS[512 + i] = b3[i];
        }
        float* w0S = (float*)(sh + SM_W0);
        for (int i = tid; i < 1024; i += THREADS) w0S[i] = W0[i];
        float* b0S = (float*)(sh + SM_B0);
        for (int i = tid; i < 256; i += THREADS) b0S[i] = b0[i];
        float* xS = (float*)(sh + SM_X);
        if (tid < 64) xS[tid] = x[blockIdx.x * 64 + tid];
    }
    __syncthreads();

    // ---- layer 0 (4 -> 256): thread t handles row t/2, col half t&1 ----
    {
        const int r = tid >> 1, cb = (tid & 1) * 128;
        const int st = r & 7;
        const float* xS = (const float*)(sh + SM_X) + (r >> 3) * 4;
        const float x0 = xS[0], x1 = xS[1], x2 = xS[2], x3 = xS[3];
        const float* w0S = (const float*)(sh + SM_W0);
        const float* b0S = (const float*)(sh + SM_B0);
#pragma unroll 4
        for (int jj = 0; jj < 128; jj += 2) {
            float vv[2];
#pragma unroll
            for (int e = 0; e < 2; e++) {
                const int j = cb + jj + e;
                const float w0 = w0S[j], w1 = w0S[256 + j];
                const float w2 = w0S[512 + j], w3 = w0S[768 + j];
                float a = b0S[j];
                a = fmaf(x0, w0, a); a = fmaf(x1, w1, a);
                a = fmaf(x2, w2, a); a = fmaf(x3, w3, a);
                const float v = ftanh(a);
                const float t = fmaf(-v, v, 1.f);
                const float m = -2.f * v * t;
                float val;
                if (st == 0) val = v;
                else if (st < 5) {
                    const float w = (st == 1) ? w0 : (st == 2) ? w1
                                   : (st == 3) ? w2 : w3;
                    val = t * w;
                } else {
                    const float w = (st == 5) ? w0 : (st == 6) ? w1 : w2;
                    val = m * w * w;
                }
                vv[e] = val;
            }
            uint32_t hi, lo;
            split_pack(vv[0], vv[1], hi, lo);
            const int boff = r * A_STRIDE + (cb + jj) * 2;
            *(uint32_t*)(sh + SM_A + boff)   = hi;
            *(uint32_t*)(sh + SM_ALO + boff) = lo;
        }
    }

    float D[2][16][4];
    uint32_t ah[2][4], al[2][4];

#pragma unroll 1
    for (int g = 0; g < 24; ++g) {
        const int l = g >> 3, c = g & 7;
        if (c == 0) {
#pragma unroll
            for (int t = 0; t < 2; t++)
#pragma unroll
                for (int nt = 0; nt < 16; nt++)
#pragma unroll
                    for (int e = 0; e < 4; e++) D[t][nt][e] = 0.f;
        }
        CP_WAIT0();
        __syncthreads();      // chunk g ready everywhere; prev compute done
        if (g + 1 < 24) { load_chunk(sb, g + 1, tid); CP_COMMIT(); }

        const uint32_t wb = sb + SM_W + (uint32_t)(g & 1) * WBUF;
#pragma unroll
        for (int ks = 0; ks < 2; ks++) {
            const int kglob = c * 32 + ks * 16;
#pragma unroll
            for (int t = 0; t < 2; t++) {
                const uint32_t ra = (uint32_t)(warpM * 32 + t * 16 + a_r) * A_STRIDE
                                  + (uint32_t)(kglob + a_k) * 2;
                ldmatrix_x4(ah[t], sb + SM_A + ra);
                ldmatrix_x4(al[t], sb + SM_ALO + ra);
            }
#pragma unroll
            for (int ntp = 0; ntp < 8; ntp++) {
                const uint32_t wa = wb
                    + (uint32_t)(warpN * 128 + ntp * 16 + w_n) * W_STRIDE
                    + (uint32_t)(ks * 16 + w_k) * 2;
                uint32_t bh[4], bl[4];
                ldmatrix_x4(bh, wa);
                ldmatrix_x4(bl, wa + 20480u);
#pragma unroll
                for (int t = 0; t < 2; t++) {
                    mma_bf16(D[t][2 * ntp],     ah[t], bh[0], bh[1]);
                    mma_bf16(D[t][2 * ntp + 1], ah[t], bh[2], bh[3]);
                    mma_bf16(D[t][2 * ntp],     al[t], bh[0], bh[1]);
                    mma_bf16(D[t][2 * ntp + 1], al[t], bh[2], bh[3]);
                    mma_bf16(D[t][2 * ntp],     ah[t], bl[0], bl[1]);
                    mma_bf16(D[t][2 * ntp + 1], ah[t], bl[2], bl[3]);
                }
            }
        }

        if (c == 7) {
            __syncthreads();   // all warps done reading A before overwrite
            const bool last = (l == 2);
            const float* bS = (const float*)(sh + SM_B) + l * 256;
#pragma unroll
            for (int t = 0; t < 2; t++) {
#pragma unroll
                for (int nt = 0; nt < 16; nt++) {
                    const int c0 = warpN * 128 + nt * 8 + 2 * tig;
                    const float d0 = D[t][nt][0], d1 = D[t][nt][1];
                    const float d2 = D[t][nt][2], d3 = D[t][nt][3];
                    const float a00 = __shfl_sync(0xffffffffu, d0, tig);
                    const float a01 = __shfl_sync(0xffffffffu, d1, tig);
                    const float a02 = __shfl_sync(0xffffffffu, d2, tig);
                    const float a03 = __shfl_sync(0xffffffffu, d3, tig);
                    const float q0 = __shfl_sync(0xffffffffu, d0, qsl);
                    const float q1 = __shfl_sync(0xffffffffu, d1, qsl);
                    const float q2 = __shfl_sync(0xffffffffu, d2, qsl);
                    const float q3 = __shfl_sync(0xffffffffu, d3, qsl);
                    const float bb0 = bS[c0], bb1 = bS[c0 + 1];
                    const float v0 = stream_val(s, d0, a00 + bb0, q0);
                    const float v1 = stream_val(s, d1, a01 + bb1, q1);
                    const float v2 = stream_val(s, d2, a02 + bb0, q2);
                    const float v3 = stream_val(s, d3, a03 + bb1, q3);
                    const int rA = warpM * 32 + t * 16 + s;
                    const int rB = rA + 8;
                    if (!last) {
                        uint32_t hi, lo;
                        split_pack(v0, v1, hi, lo);
                        int bo_ = rA * A_STRIDE + c0 * 2;
                        *(uint32_t*)(sh + SM_A + bo_)   = hi;
                        *(uint32_t*)(sh + SM_ALO + bo_) = lo;
                        split_pack(v2, v3, hi, lo);
                        bo_ = rB * A_STRIDE + c0 * 2;
                        *(uint32_t*)(sh + SM_A + bo_)   = hi;
                        *(uint32_t*)(sh + SM_ALO + bo_) = lo;
                    } else {
                        float* vp = (float*)sh;
                        vp[rA * V_STRIDE + c0]     = v0;
                        vp[rA * V_STRIDE + c0 + 1] = v1;
                        vp[rB * V_STRIDE + c0]     = v2;
                        vp[rB * V_STRIDE + c0 + 1] = v3;
                    }
                }
            }
        }
    }
    __syncthreads();

    // ---- output layer (256 -> 2): warp handles samples 2w, 2w+1 ----
    const float* vals = (const float*)sh;
    const float* woS = (const float*)(sh + SM_WO);
    const float bo0 = bo[0], bo1 = bo[1];
#pragma unroll 1
    for (int i = 0; i < 2; i++) {
        const int smp = warp * 2 + i;
        float r[8][2];
#pragma unroll
        for (int rr = 0; rr < 8; rr++) { r[rr][0] = 0.f; r[rr][1] = 0.f; }
#pragma unroll
        for (int it = 0; it < 8; it++) {
            const int k = lane + it * 32;
            const float wv0 = woS[2 * k], wv1 = woS[2 * k + 1];
#pragma unroll
            for (int st = 0; st < 8; st++) {
                const float h = vals[(smp * 8 + st) * V_STRIDE + k];
                r[st][0] = fmaf(h, wv0, r[st][0]);
                r[st][1] = fmaf(h, wv1, r[st][1]);
            }
        }
#pragma unroll
        for (int rr = 0; rr < 8; rr++) {
#pragma unroll
            for (int off = 16; off > 0; off >>= 1) {
                r[rr][0] += __shfl_xor_sync(0xffffffffu, r[rr][0], off);
                r[rr][1] += __shfl_xor_sync(0xffffffffu, r[rr][1], off);
            }
        }
        if (lane == 0) {
            const int gs = blockIdx.x * SPC + smp;
            const float cc  = r[0][0] + bo0;
            const float Fi  = r[0][1] + bo1;
            const float cg0 = r[1][0], cg1 = r[2][0], cg2 = r[3][0];
            const float fg0 = r[1][1], fg1 = r[2][1], fg2 = r[3][1];
            const float c_t = r[4][0];
            const float trHc = r[5][0] + r[6][0] + r[7][0];
            const float fila = r[5][1] + r[6][1] + r[7][1];
            const float jdiv = -trHc
                               - (cg0 * fg0 + cg1 * fg1 + cg2 * fg2 + cc * fila)
                               + 0.1f * (cg0 + cg1 + cg2);
            const int B = BATCH;
            out[gs]                 = cc;
            out[B + gs]             = c_t;
            out[2 * B + gs * 3 + 0] = cg0;
            out[2 * B + gs * 3 + 1] = cg1;
            out[2 * B + gs * 3 + 2] = cg2;
            out[5 * B + gs]         = Fi;
            out[6 * B + gs * 3 + 0] = fg0;
            out[6 * B + gs * 3 + 1] = fg1;
            out[6 * B + gs * 3 + 2] = fg2;
            out[9 * B + gs]         = fila;
            out[10 * B + gs]        = jdiv;
        }
    }
}

extern "C" void kernel_launch(void* const* d_in, const int* in_sizes, int n_in,
                              void* d_out, int out_size) {
    const float* x  = (const float*)d_in[0];
    const float* W0 = (const float*)d_in[1];
    const float* b0 = (const float*)d_in[2];
    const float* W1 = (const float*)d_in[3];
    const float* b1 = (const float*)d_in[4];
    const float* W2 = (const float*)d_in[5];
    const float* b2 = (const float*)d_in[6];
    const float* W3 = (const float*)d_in[7];
    const float* b3 = (const float*)d_in[8];
    const float* Wo = (const float*)d_in[9];
    const float* bo = (const float*)d_in[10];

    prep_weights<<<768, 256>>>(W1, W2, W3);

    cudaFuncSetAttribute(grad_mlp_tc,
                         cudaFuncAttributeMaxDynamicSharedMemorySize, SMEM_TOTAL);
    grad_mlp_tc<<<NBLK, THREADS, SMEM_TOTAL>>>(
        x, W0, b0, b1, b2, b3, Wo, bo, (float*)d_out);
}

// round 16
// speedup vs baseline: 2.1566x; 2.1566x over previous
#include <cuda_runtime.h>
#include <cuda_bf16.h>
#include <cstdint>

#define BATCH   16384
#define SPC     16              // samples per CTA -> M = 128 rows
#define NBLK    (BATCH / SPC)   // 1024
#define THREADS 512

// ---- SMEM layout (bytes) ----
#define SM_A     0              // A hi: 128 rows x 528 B (264 bf16, padded)
#define A_STRIDE 528
#define SM_ALO   67584          // A lo: same shape
#define SM_W     135168         // 2 bufs x (whi 20480 + wlo 20480)
#define W_STRIDE 80             // 40 bf16 padded row (32 used)
#define WBUF     40960
#define SM_WO    217088         // float[512]
#define SM_B     219136         // float[3][256]
#define SM_W0    222208         // float[4][256]
#define SM_B0    226304         // float[256]
#define SM_X     227328         // float[64]
#define SMEM_TOTAL 227584
// vals overlay (final layer, fp32): rows 128 x 264 floats over [SM_A, SM_A+135168)
#define V_STRIDE 264

// weight scratch: [layer(3)][hi/lo(2)][n(256)][k(256)] bf16  (W^T: [n][k] = W[k][n])
__device__ __nv_bfloat16 g_wsplit[3][2][256][256];

// ============================ helpers ============================
__device__ __forceinline__ uint32_t smem_to_u32(const void* p) {
    uint32_t a;
    asm("{ .reg .u64 t; cvta.to.shared.u64 t, %1; cvt.u32.u64 %0, t; }"
        : "=r"(a) : "l"(p));
    return a;
}
__device__ __forceinline__ void cp_async16(uint32_t dst, const void* src) {
    asm volatile("cp.async.cg.shared.global [%0], [%1], 16;" :: "r"(dst), "l"(src));
}
#define CP_COMMIT() asm volatile("cp.async.commit_group;" ::: "memory")
#define CP_WAIT0()  asm volatile("cp.async.wait_group 0;" ::: "memory")

__device__ __forceinline__ void ldmatrix_x4(uint32_t* f, uint32_t addr) {
    asm volatile("ldmatrix.sync.aligned.m8n8.x4.shared.b16 {%0,%1,%2,%3}, [%4];"
        : "=r"(f[0]), "=r"(f[1]), "=r"(f[2]), "=r"(f[3]) : "r"(addr));
}
__device__ __forceinline__ void mma_bf16(float* d, const uint32_t* a,
                                         uint32_t b0, uint32_t b1) {
    asm volatile("mma.sync.aligned.m16n8k16.row.col.f32.bf16.bf16.f32 "
        "{%0,%1,%2,%3}, {%4,%5,%6,%7}, {%8,%9}, {%0,%1,%2,%3};"
        : "+f"(d[0]), "+f"(d[1]), "+f"(d[2]), "+f"(d[3])
        : "r"(a[0]), "r"(a[1]), "r"(a[2]), "r"(a[3]), "r"(b0), "r"(b1));
}

// fast accurate tanh: (e-1)/(e+1), e = exp(2a), clamped
__device__ __forceinline__ float ftanh(float a) {
    float ac = fminf(fmaxf(a, -40.f), 40.f);
    float e = __expf(2.f * ac);
    return __fdividef(e - 1.f, e + 1.f);
}
// coupled stream value: s=0 -> tanh; 1..4 -> t*a'; 5..7 -> t*a'' - 2 v t q^2
__device__ __forceinline__ float stream_val(int s, float d, float a0, float q) {
    const float v = ftanh(a0);
    const float tt = fmaf(-v, v, 1.f);
    if (s == 0) return v;
    if (s < 5)  return tt * d;
    return fmaf(tt, d, (-2.f * v * tt) * q * q);
}
// split fp32 pair -> packed bf16x2 hi and lo
__device__ __forceinline__ void split_pack(float v0, float v1,
                                           uint32_t& hi, uint32_t& lo) {
    __nv_bfloat16 h0 = __float2bfloat16(v0);
    __nv_bfloat16 h1 = __float2bfloat16(v1);
    __nv_bfloat16 l0 = __float2bfloat16(v0 - __bfloat162float(h0));
    __nv_bfloat16 l1 = __float2bfloat16(v1 - __bfloat162float(h1));
    __nv_bfloat162 hp(h0, h1), lp(l0, l1);
    hi = *reinterpret_cast<uint32_t*>(&hp);
    lo = *reinterpret_cast<uint32_t*>(&lp);
}

// ============================ prep kernel ============================
__global__ void prep_weights(const float* __restrict__ W1,
                             const float* __restrict__ W2,
                             const float* __restrict__ W3) {
    int l = blockIdx.x >> 8, n = blockIdx.x & 255, k = threadIdx.x;
    const float* W = (l == 0) ? W1 : (l == 1) ? W2 : W3;
    float w = W[k * 256 + n];
    __nv_bfloat16 hi = __float2bfloat16(w);
    g_wsplit[l][0][n][k] = hi;
    g_wsplit[l][1][n][k] = __float2bfloat16(w - __bfloat162float(hi));
}

// stream W chunk g (layer g/8, k-chunk g%8) into buffer g&1
__device__ __forceinline__ void load_chunk(uint32_t sb, int g, int tid) {
    const int l = g >> 3, c = g & 7;
    const __nv_bfloat16* base = &g_wsplit[0][0][0][0];
#pragma unroll
    for (int t = 0; t < 4; t++) {
        int i = tid + t * 512;
        int split = i >> 10, r = i & 1023, n = r >> 2, seg = r & 3;
        const __nv_bfloat16* src =
            base + (((size_t)(l * 2 + split)) << 16) + n * 256 + c * 32 + seg * 8;
        uint32_t dst = sb + SM_W + (uint32_t)(g & 1) * WBUF +
                       (uint32_t)split * 20480u + (uint32_t)n * W_STRIDE +
                       (uint32_t)seg * 16u;
        cp_async16(dst, src);
    }
}

// ============================ main kernel ============================
extern "C" __global__ void __launch_bounds__(THREADS, 1)
grad_mlp_tc(const float* __restrict__ x,
            const float* __restrict__ W0, const float* __restrict__ b0,
            const float* __restrict__ b1, const float* __restrict__ b2,
            const float* __restrict__ b3,
            const float* __restrict__ Wo, const float* __restrict__ bo,
            float* __restrict__ out) {
    extern __shared__ char sh[];
    const uint32_t sb = smem_to_u32(sh);
    const int tid = threadIdx.x;
    const int warp = tid >> 5, lane = tid & 31;
    const int warpM = warp >> 2, warpN = warp & 3;   // 4 x 4 warp grid
    const int s = lane >> 2;             // stream id of this thread's D rows
    const int tig = lane & 3;
    const int qsl = ((s >= 5) ? (s - 4) : 0) * 4 + tig;   // shfl src for q
    // ldmatrix lane address components
    const int a_r = lane & 15;
    const int a_k = (lane >> 4) * 8;
    const int w_n = (lane & 7) + ((lane & 16) ? 8 : 0);
    const int w_k = (lane & 8) ? 8 : 0;

    // prefetch first weight chunk
    load_chunk(sb, 0, tid);
    CP_COMMIT();

    // stage small tables
    {
        float* woS = (float*)(sh + SM_WO);
        for (int i = tid; i < 512; i += THREADS) woS[i] = Wo[i];
        float* bS = (float*)(sh + SM_B);
        for (int i = tid; i < 256; i += THREADS) {
            bS[i] = b1[i]; bS[256 + i] = b2[i]; bS[512 + i] = b3[i];
        }
        float* w0S = (float*)(sh + SM_W0);
        for (int i = tid; i < 1024; i += THREADS) w0S[i] = W0[i];
        float* b0S = (float*)(sh + SM_B0);
        for (int i = tid; i < 256; i += THREADS) b0S[i] = b0[i];
        float* xS = (float*)(sh + SM_X);
        if (tid < 64) xS[tid] = x[blockIdx.x * 64 + tid];
    }
    __syncthreads();

    // ---- layer 0 (4 -> 256): thread t handles row t/4, col quarter t&3 ----
    {
        const int r = tid >> 2, cb = (tid & 3) * 64;
        const int st = r & 7;
        const float* xS = (const float*)(sh + SM_X) + (r >> 3) * 4;
        const float x0 = xS[0], x1 = xS[1], x2 = xS[2], x3 = xS[3];
        const float* w0S = (const float*)(sh + SM_W0);
        const float* b0S = (const float*)(sh + SM_B0);
#pragma unroll 4
        for (int jj = 0; jj < 64; jj += 2) {
            float vv[2];
#pragma unroll
            for (int e = 0; e < 2; e++) {
                const int j = cb + jj + e;
                const float w0 = w0S[j], w1 = w0S[256 + j];
                const float w2 = w0S[512 + j], w3 = w0S[768 + j];
                float a = b0S[j];
                a = fmaf(x0, w0, a); a = fmaf(x1, w1, a);
                a = fmaf(x2, w2, a); a = fmaf(x3, w3, a);
                const float v = ftanh(a);
                const float t = fmaf(-v, v, 1.f);
                const float m = -2.f * v * t;
                float val;
                if (st == 0) val = v;
                else if (st < 5) {
                    const float w = (st == 1) ? w0 : (st == 2) ? w1
                                   : (st == 3) ? w2 : w3;
                    val = t * w;
                } else {
                    const float w = (st == 5) ? w0 : (st == 6) ? w1 : w2;
                    val = m * w * w;
                }
                vv[e] = val;
            }
            uint32_t hi, lo;
            split_pack(vv[0], vv[1], hi, lo);
            const int boff = r * A_STRIDE + (cb + jj) * 2;
            *(uint32_t*)(sh + SM_A + boff)   = hi;
            *(uint32_t*)(sh + SM_ALO + boff) = lo;
        }
    }

    float D[2][8][4];
    uint32_t ah[2][4], al[2][4];

#pragma unroll 1
    for (int g = 0; g < 24; ++g) {
        const int l = g >> 3, c = g & 7;
        if (c == 0) {
#pragma unroll
            for (int t = 0; t < 2; t++)
#pragma unroll
                for (int nt = 0; nt < 8; nt++)
#pragma unroll
                    for (int e = 0; e < 4; e++) D[t][nt][e] = 0.f;
        }
        CP_WAIT0();
        __syncthreads();      // chunk g ready everywhere; prev compute done
        if (g + 1 < 24) { load_chunk(sb, g + 1, tid); CP_COMMIT(); }

        const uint32_t wb = sb + SM_W + (uint32_t)(g & 1) * WBUF;
#pragma unroll
        for (int ks = 0; ks < 2; ks++) {
            const int kglob = c * 32 + ks * 16;
#pragma unroll
            for (int t = 0; t < 2; t++) {
                const uint32_t ra = (uint32_t)(warpM * 32 + t * 16 + a_r) * A_STRIDE
                                  + (uint32_t)(kglob + a_k) * 2;
                ldmatrix_x4(ah[t], sb + SM_A + ra);
                ldmatrix_x4(al[t], sb + SM_ALO + ra);
            }
#pragma unroll
            for (int ntp = 0; ntp < 4; ntp++) {
                const uint32_t wa = wb
                    + (uint32_t)(warpN * 64 + ntp * 16 + w_n) * W_STRIDE
                    + (uint32_t)(ks * 16 + w_k) * 2;
                uint32_t bh[4], bl[4];
                ldmatrix_x4(bh, wa);
                ldmatrix_x4(bl, wa + 20480u);
                // pass-major ordering: 4 independent tiles between dependent reuses
                mma_bf16(D[0][2 * ntp],     ah[0], bh[0], bh[1]);
                mma_bf16(D[0][2 * ntp + 1], ah[0], bh[2], bh[3]);
                mma_bf16(D[1][2 * ntp],     ah[1], bh[0], bh[1]);
                mma_bf16(D[1][2 * ntp + 1], ah[1], bh[2], bh[3]);
                mma_bf16(D[0][2 * ntp],     al[0], bh[0], bh[1]);
                mma_bf16(D[0][2 * ntp + 1], al[0], bh[2], bh[3]);
                mma_bf16(D[1][2 * ntp],     al[1], bh[0], bh[1]);
                mma_bf16(D[1][2 * ntp + 1], al[1], bh[2], bh[3]);
                mma_bf16(D[0][2 * ntp],     ah[0], bl[0], bl[1]);
                mma_bf16(D[0][2 * ntp + 1], ah[0], bl[2], bl[3]);
                mma_bf16(D[1][2 * ntp],     ah[1], bl[0], bl[1]);
                mma_bf16(D[1][2 * ntp + 1], ah[1], bl[2], bl[3]);
            }
        }

        if (c == 7) {
            __syncthreads();   // all warps done reading A before overwrite
            const bool last = (l == 2);
            const float* bS = (const float*)(sh + SM_B) + l * 256;
#pragma unroll
            for (int t = 0; t < 2; t++) {
#pragma unroll
                for (int nt = 0; nt < 8; nt++) {
                    const int c0 = warpN * 64 + nt * 8 + 2 * tig;
                    const float d0 = D[t][nt][0], d1 = D[t][nt][1];
                    const float d2 = D[t][nt][2], d3 = D[t][nt][3];
                    const float a00 = __shfl_sync(0xffffffffu, d0, tig);
                    const float a01 = __shfl_sync(0xffffffffu, d1, tig);
                    const float a02 = __shfl_sync(0xffffffffu, d2, tig);
                    const float a03 = __shfl_sync(0xffffffffu, d3, tig);
                    const float q0 = __shfl_sync(0xffffffffu, d0, qsl);
                    const float q1 = __shfl_sync(0xffffffffu, d1, qsl);
                    const float q2 = __shfl_sync(0xffffffffu, d2, qsl);
                    const float q3 = __shfl_sync(0xffffffffu, d3, qsl);
                    const float bb0 = bS[c0], bb1 = bS[c0 + 1];
                    const float v0 = stream_val(s, d0, a00 + bb0, q0);
                    const float v1 = stream_val(s, d1, a01 + bb1, q1);
                    const float v2 = stream_val(s, d2, a02 + bb0, q2);
                    const float v3 = stream_val(s, d3, a03 + bb1, q3);
                    const int rA = warpM * 32 + t * 16 + s;
                    const int rB = rA + 8;
                    if (!last) {
                        uint32_t hi, lo;
                        split_pack(v0, v1, hi, lo);
                        int bo_ = rA * A_STRIDE + c0 * 2;
                        *(uint32_t*)(sh + SM_A + bo_)   = hi;
                        *(uint32_t*)(sh + SM_ALO + bo_) = lo;
                        split_pack(v2, v3, hi, lo);
                        bo_ = rB * A_STRIDE + c0 * 2;
                        *(uint32_t*)(sh + SM_A + bo_)   = hi;
                        *(uint32_t*)(sh + SM_ALO + bo_) = lo;
                    } else {
                        float* vp = (float*)sh;
                        vp[rA * V_STRIDE + c0]     = v0;
                        vp[rA * V_STRIDE + c0 + 1] = v1;
                        vp[rB * V_STRIDE + c0]     = v2;
                        vp[rB * V_STRIDE + c0 + 1] = v3;
                    }
                }
            }
        }
    }
    __syncthreads();

    // ---- output layer (256 -> 2): warp w handles sample w (16 warps) ----
    const float* vals = (const float*)sh;
    const float* woS = (const float*)(sh + SM_WO);
    const float bo0 = bo[0], bo1 = bo[1];
    {
        const int smp = warp;
        float r[8][2];
#pragma unroll
        for (int rr = 0; rr < 8; rr++) { r[rr][0] = 0.f; r[rr][1] = 0.f; }
#pragma unroll
        for (int it = 0; it < 8; it++) {
            const int k = lane + it * 32;
            const float wv0 = woS[2 * k], wv1 = woS[2 * k + 1];
#pragma unroll
            for (int st = 0; st < 8; st++) {
                const float h = vals[(smp * 8 + st) * V_STRIDE + k];
                r[st][0] = fmaf(h, wv0, r[st][0]);
                r[st][1] = fmaf(h, wv1, r[st][1]);
            }
        }
#pragma unroll
        for (int rr = 0; rr < 8; rr++) {
#pragma unroll
            for (int off = 16; off > 0; off >>= 1) {
                r[rr][0] += __shfl_xor_sync(0xffffffffu, r[rr][0], off);
                r[rr][1] += __shfl_xor_sync(0xffffffffu, r[rr][1], off);
            }
        }
        if (lane == 0) {
            const int gs = blockIdx.x * SPC + smp;
            const float cc  = r[0][0] + bo0;
            const float Fi  = r[0][1] + bo1;
            const float cg0 = r[1][0], cg1 = r[2][0], cg2 = r[3][0];
            const float fg0 = r[1][1], fg1 = r[2][1], fg2 = r[3][1];
            const float c_t = r[4][0];
            const float trHc = r[5][0] + r[6][0] + r[7][0];
            const float fila = r[5][1] + r[6][1] + r[7][1];
            const float jdiv = -trHc
                               - (cg0 * fg0 + cg1 * fg1 + cg2 * fg2 + cc * fila)
                               + 0.1f * (cg0 + cg1 + cg2);
            const int B = BATCH;
            out[gs]                 = cc;
            out[B + gs]             = c_t;
            out[2 * B + gs * 3 + 0] = cg0;
            out[2 * B + gs * 3 + 1] = cg1;
            out[2 * B + gs * 3 + 2] = cg2;
            out[5 * B + gs]         = Fi;
            out[6 * B + gs * 3 + 0] = fg0;
            out[6 * B + gs * 3 + 1] = fg1;
            out[6 * B + gs * 3 + 2] = fg2;
            out[9 * B + gs]         = fila;
            out[10 * B + gs]        = jdiv;
        }
    }
}

extern "C" void kernel_launch(void* const* d_in, const int* in_sizes, int n_in,
                              void* d_out, int out_size) {
    const float* x  = (const float*)d_in[0];
    const float* W0 = (const float*)d_in[1];
    const float* b0 = (const float*)d_in[2];
    const float* W1 = (const float*)d_in[3];
    const float* b1 = (const float*)d_in[4];
    const float* W2 = (const float*)d_in[5];
    const float* b2 = (const float*)d_in[6];
    const float* W3 = (const float*)d_in[7];
    const float* b3 = (const float*)d_in[8];
    const float* Wo = (const float*)d_in[9];
    const float* bo = (const float*)d_in[10];

    prep_weights<<<768, 256>>>(W1, W2, W3);

    cudaFuncSetAttribute(grad_mlp_tc,
                         cudaFuncAttributeMaxDynamicSharedMemorySize, SMEM_TOTAL);
    grad_mlp_tc<<<NBLK, THREADS, SMEM_TOTAL>>>(
        x, W0, b0, b1, b2, b3, Wo, bo, (float*)d_out);
}